// round 4
// baseline (speedup 1.0000x reference)
#include <cuda_runtime.h>
#include <cstdint>

#define N_MAX 100000
#define E_MAX 3200000

// Scratch: __device__ globals (no allocation allowed)
__device__ float g_deg[N_MAX];
__device__ float g_dinv[N_MAX];
__device__ int   g_count[N_MAX];
__device__ int   g_offsets[N_MAX + 1];
__device__ int   g_cursor[N_MAX];
__device__ unsigned long long g_perm[E_MAX];   // packed (row:int32 | coef:f32)
__device__ int   g_is64;                       // 1 if edge_index is int64, else int32

// Read edge index #pos from a buffer of unknown dtype (int64 vs int32).
__device__ __forceinline__ int get_idx(const void* ei, int is64, long pos) {
    if (is64) return (int)((const long long*)ei)[pos];
    return ((const int*)ei)[pos];
}

// ---------------------------------------------------------------------------
// 0) dtype detect: int64 indices < 2^31 have all-zero odd 32-bit words.
__global__ void k_detect(const unsigned int* __restrict__ w) {
    if (threadIdx.x == 0 && blockIdx.x == 0) {
        int all0 = 1;
        #pragma unroll
        for (int i = 0; i < 64; i++) all0 &= (w[2 * i + 1] == 0u);
        g_is64 = all0;
    }
}

// 1) deg = 1.0 (self loop), count = 0
__global__ void k_setup(int n) {
    int i = blockIdx.x * blockDim.x + threadIdx.x;
    if (i < n) { g_deg[i] = 1.0f; g_count[i] = 0; }
}

// 2) per edge: deg[col] += ew ; count[col] += 1
__global__ void k_count_deg(const void* __restrict__ ei,
                            const float* __restrict__ ew, int E) {
    int e = blockIdx.x * blockDim.x + threadIdx.x;
    if (e < E) {
        int is64 = g_is64;
        int c = get_idx(ei, is64, (long)E + e);
        atomicAdd(&g_deg[c], ew[e]);
        atomicAdd(&g_count[c], 1);
    }
}

// 3) dinv = rsqrt(deg)
__global__ void k_dinv(int n) {
    int i = blockIdx.x * blockDim.x + threadIdx.x;
    if (i < n) {
        float d = g_deg[i];
        g_dinv[i] = (d > 0.0f) ? rsqrtf(d) : 0.0f;
    }
}

// 4) single-block exclusive scan: offsets[i] = sum_{j<i} count[j]; cursor = offsets
__global__ void k_scan(int n, int E) {
    __shared__ int s[1024];
    int t = threadIdx.x;
    int chunk = (n + 1023) / 1024;
    int lo = t * chunk;
    int hi = lo + chunk; if (hi > n) hi = n;

    int sum = 0;
    for (int i = lo; i < hi; i++) sum += g_count[i];
    s[t] = sum;
    __syncthreads();
    for (int d = 1; d < 1024; d <<= 1) {
        int v = (t >= d) ? s[t - d] : 0;
        __syncthreads();
        s[t] += v;
        __syncthreads();
    }
    int run = (t == 0) ? 0 : s[t - 1];
    for (int i = lo; i < hi; i++) {
        g_offsets[i] = run;
        g_cursor[i]  = run;
        run += g_count[i];
    }
    if (t == 0) g_offsets[n] = E;
}

// 5) fill CSR: per edge, compute coef and scatter packed record under col bucket
__global__ void k_fill(const void* __restrict__ ei,
                       const float* __restrict__ ew, int E) {
    int e = blockIdx.x * blockDim.x + threadIdx.x;
    if (e < E) {
        int is64 = g_is64;
        int r = get_idx(ei, is64, e);
        int c = get_idx(ei, is64, (long)E + e);
        float coef = g_dinv[r] * ew[e] * g_dinv[c];
        int pos = atomicAdd(&g_cursor[c], 1);
        unsigned long long rec =
            (unsigned long long)(unsigned int)r |
            ((unsigned long long)__float_as_uint(coef) << 32);
        g_perm[pos] = rec;
    }
}

// 6) gather: one warp per node. lane l owns float4 chunk l of the 128-d row.
//    out[c] = dinv[c]^2 * x[c] + sum_{e in CSR[c]} coef_e * x[row_e]
__global__ void k_gather(const float4* __restrict__ x,
                         float4* __restrict__ out, int n) {
    int w    = (blockIdx.x * blockDim.x + threadIdx.x) >> 5;
    int lane = threadIdx.x & 31;
    if (w >= n) return;

    float di = g_dinv[w];
    float s  = di * di;
    float4 v = __ldg(&x[(long)w * 32 + lane]);
    float4 acc;
    acc.x = v.x * s; acc.y = v.y * s; acc.z = v.z * s; acc.w = v.w * s;

    int beg = g_offsets[w];
    int end = g_offsets[w + 1];

    if (beg < end) {
        unsigned long long rec = g_perm[beg];   // software pipeline: prefetch rec
        for (int j = beg; j < end; j++) {
            unsigned long long next = (j + 1 < end) ? g_perm[j + 1] : 0ull;
            int   r  = (int)(unsigned int)(rec & 0xFFFFFFFFull);
            float cw = __uint_as_float((unsigned int)(rec >> 32));
            float4 xv = __ldg(&x[(long)r * 32 + lane]);
            acc.x += cw * xv.x;
            acc.y += cw * xv.y;
            acc.z += cw * xv.z;
            acc.w += cw * xv.w;
            rec = next;
        }
    }
    out[(long)w * 32 + lane] = acc;
}

// ---------------------------------------------------------------------------
extern "C" void kernel_launch(void* const* d_in, const int* in_sizes, int n_in,
                              void* d_out, int out_size) {
    // Bind inputs BY ELEMENT COUNT (robust to metadata ordering):
    //   x: N*128 f32 ; edge_weight: E f32 ; edge_index: 2E (i64 or i32 -- detected on device)
    int n = out_size / 128;

    const float* x = nullptr;
    int xi = -1;
    for (int i = 0; i < n_in; i++) {
        if (in_sizes[i] == n * 128) { x = (const float*)d_in[i]; xi = i; break; }
    }
    int ia = -1, ib = -1;
    for (int i = 0; i < n_in; i++) {
        if (i == xi) continue;
        if (ia < 0) ia = i; else ib = i;
    }
    const void* ei;
    const float* ew;
    int E;
    if (in_sizes[ia] > in_sizes[ib]) {
        ei = d_in[ia]; ew = (const float*)d_in[ib]; E = in_sizes[ib];
    } else {
        ei = d_in[ib]; ew = (const float*)d_in[ia]; E = in_sizes[ia];
    }

    float* out = (float*)d_out;

    k_detect   <<<1, 32>>>((const unsigned int*)ei);
    k_setup    <<<(n + 255) / 256, 256>>>(n);
    k_count_deg<<<(E + 255) / 256, 256>>>(ei, ew, E);
    k_dinv     <<<(n + 255) / 256, 256>>>(n);
    k_scan     <<<1, 1024>>>(n, E);
    k_fill     <<<(E + 255) / 256, 256>>>(ei, ew, E);

    long long gt = (long long)n * 32;
    k_gather   <<<(int)((gt + 255) / 256), 256>>>((const float4*)x, (float4*)out, n);
}